// round 7
// baseline (speedup 1.0000x reference)
#include <cuda_runtime.h>
#include <math.h>

// ---------------- problem constants ----------------
#define Bz   4
#define Sz   256
#define Dz   300
#define Hz   256
#define H4z  1024
#define Lz   10
#define AGGz 62
#define NCLSz 22
#define FEATN 1626          // 4*H + 2 + 2*D
#define BSH  (Bz*Sz*Hz)     // 262144
#define BSS  (Bz*Sz*Sz)     // 262144
#define EPSf 1e-8f

// ---------------- scratch layout (floats) ----------------
constexpr long long OFF_WIHT_CF = 0;
constexpr long long OFF_WIHT_CB = OFF_WIHT_CF + (long long)Dz*H4z;
constexpr long long OFF_WIHT_AF = OFF_WIHT_CB + (long long)Dz*H4z;
constexpr long long OFF_WIHT_AB = OFF_WIHT_AF + (long long)AGGz*H4z;
constexpr long long OFF_FC1WT   = OFF_WIHT_AB + (long long)AGGz*H4z;
constexpr long long OFF_PRE_CTX = OFF_FC1WT + (long long)FEATN*512;
constexpr long long OFF_HS      = OFF_PRE_CTX + 4LL*Bz*Sz*H4z;   // p_fw,p_bw,h_fw,h_bw
constexpr long long OFF_NRM     = OFF_HS + 4LL*BSH;              // (4,B,S)
constexpr long long OFF_ATT     = OFF_NRM + 4LL*Bz*Sz;           // (2,B,S,S)
constexpr long long OFF_ROWSUM  = OFF_ATT + 2LL*BSS;             // (2,B,S)
constexpr long long OFF_COLSUM  = OFF_ROWSUM + 2LL*Bz*Sz;        // (2,B,S)
constexpr long long OFF_STATS   = OFF_COLSUM + 2LL*Bz*Sz;        // (4 kinds x 2 dirs, B,S,H)
constexpr long long OFF_NLW     = OFF_STATS + 8LL*BSH;           // (2 which,2 dir,B,S,L)
constexpr long long OFF_MVP     = OFF_NLW + 4LL*Bz*Sz*Lz;        // (B,S,62)
constexpr long long OFF_MVH     = OFF_MVP + (long long)Bz*Sz*AGGz;
constexpr long long OFF_PRE_AGG = OFF_MVH + (long long)Bz*Sz*AGGz;
constexpr long long OFF_HT      = OFF_PRE_AGG + 4LL*Bz*Sz*H4z;   // (4,B,H)
constexpr long long OFF_MEANS   = OFF_HT + 4LL*Bz*Hz;            // (2,B,D)
constexpr long long OFF_FC1O    = OFF_MEANS + 2LL*Bz*Dz;         // (B,512)
constexpr long long SCRATCH_N   = OFF_FC1O + (long long)Bz*512 + 64;

__device__ __align__(256) float g_s[SCRATCH_N];
__device__ __align__(128) int g_flag[16*8];        // per (unit, slice) step flags
__device__ __align__(256) float g_hbuf[2*16*Hz];   // double-buffered h exchange

__device__ __forceinline__ float sigmf_(float x){ return 1.f/(1.f+expf(-x)); }

__device__ __forceinline__ float warp_sum(float v){
    #pragma unroll
    for (int o = 16; o > 0; o >>= 1) v += __shfl_down_sync(0xffffffffu, v, o);
    return v;
}
__device__ __forceinline__ float warp_max(float v){
    #pragma unroll
    for (int o = 16; o > 0; o >>= 1) v = fmaxf(v, __shfl_down_sync(0xffffffffu, v, o));
    return v;
}

// two transposes in one launch: z selects (src, dst); src (R,C) -> g_s[dst] as (C,R)
__global__ void transpose2_kernel(const float* __restrict__ s0, const float* __restrict__ s1,
                                  long long d0, long long d1, int R, int C){
    const float* src = blockIdx.z ? s1 : s0;
    long long dst = blockIdx.z ? d1 : d0;
    long long total = (long long)R*C;
    for (long long i = blockIdx.x*(long long)blockDim.x + threadIdx.x; i < total;
         i += (long long)gridDim.x*blockDim.x){
        int r = (int)(i / C), c = (int)(i % C);
        g_s[dst + (long long)c*R + r] = src[i];
    }
}

// single transpose (fc1)
__global__ void transpose_kernel(const float* __restrict__ src, long long dst_off, int R, int C){
    long long total = (long long)R*C;
    for (long long i = blockIdx.x*(long long)blockDim.x + threadIdx.x; i < total;
         i += (long long)gridDim.x*blockDim.x){
        int r = (int)(i / C), c = (int)(i % C);
        g_s[dst_off + (long long)c*R + r] = src[i];
    }
}

// Batched GEMM over z=0..3: C_z(MxN) = A_z(MxK) * Bt_z(KxN) + bias_z(N)
__global__ void __launch_bounds__(256) gemm4_kernel(
        const float* __restrict__ A0, const float* __restrict__ A1,
        long long a0_off, long long a1_off,
        long long bt_base, long long bt_stride,
        const float* __restrict__ biasF, const float* __restrict__ biasB,
        long long c_off, int M, int N, int K){
    int z = blockIdx.z;
    const float* A  = (z < 2) ? (A0 ? A0 : (g_s + a0_off)) : (A1 ? A1 : (g_s + a1_off));
    const float* Bt = g_s + bt_base + (long long)(z & 1)*bt_stride;
    const float* bias = (z & 1) ? biasB : biasF;
    float* C = g_s + c_off + (long long)z*M*N;
    __shared__ float As[16][64];
    __shared__ float Bs[16][64];
    int bm = blockIdx.y*64, bn = blockIdx.x*64;
    int tid = threadIdx.x;
    int tr = tid >> 4, tc = tid & 15;
    float acc[4][4] = {};
    for (int k0 = 0; k0 < K; k0 += 16){
        for (int i = tid; i < 1024; i += 256){
            int m = i >> 4, k = i & 15;
            As[k][m] = (k0+k < K) ? A[(long long)(bm+m)*K + k0 + k] : 0.f;
        }
        for (int i = tid; i < 1024; i += 256){
            int k = i >> 6, n = i & 63;
            Bs[k][n] = (k0+k < K) ? Bt[(long long)(k0+k)*N + bn + n] : 0.f;
        }
        __syncthreads();
        #pragma unroll
        for (int k = 0; k < 16; k++){
            float a[4], bv[4];
            #pragma unroll
            for (int i = 0; i < 4; i++) a[i]  = As[k][tr*4+i];
            #pragma unroll
            for (int j = 0; j < 4; j++) bv[j] = Bs[k][tc*4+j];
            #pragma unroll
            for (int i = 0; i < 4; i++)
                #pragma unroll
                for (int j = 0; j < 4; j++) acc[i][j] = fmaf(a[i], bv[j], acc[i][j]);
        }
        __syncthreads();
    }
    #pragma unroll
    for (int i = 0; i < 4; i++){
        int m = bm + tr*4 + i;
        #pragma unroll
        for (int j = 0; j < 4; j++){
            int n = bn + tc*4 + j;
            C[(long long)m*N + n] = acc[i][j] + bias[n];
        }
    }
}

// zero cross-block sync state before each LSTM launch (graph-deterministic)
__global__ void zero_sync_kernel(){
    int t = threadIdx.x;
    if (t < 16*8) g_flag[t] = 0;
    for (int i = t; i < 2*16*Hz; i += 256) g_hbuf[i] = 0.f;
}

// Register-resident LSTM: grid=128 (16 units x 8 slices), 256 threads.
// Block owns 32 hidden units (all 4 gates) = 128 weight rows in registers.
// Double-buffered h exchange in L2; per-unit flag-array barrier (8 parallel flags).
__global__ void __launch_bounds__(256,1) lstm2_kernel(int stage,
        const float* __restrict__ Whh_f, const float* __restrict__ Whh_b){
    int unit = blockIdx.x >> 3, slice = blockIdx.x & 7;
    int grp = unit >> 3, dir = (unit >> 2) & 1, b = unit & 3;
    long long chunk = (long long)(grp*2 + dir)*Bz + b;
    const float* pre = g_s + (stage ? OFF_PRE_AGG : OFF_PRE_CTX) + chunk*(long long)Sz*H4z;
    const float* Whh = dir ? Whh_b : Whh_f;
    float* hs = g_s + OFF_HS + chunk*(long long)Sz*Hz;

    int t = threadIdx.x;
    int kw = t >> 5, l = t & 31;

    // weight tile -> registers: rows rho=4l..4l+3, k in [kw*32, kw*32+32)
    float wr[4][32];
    #pragma unroll
    for (int j = 0; j < 4; j++){
        int rho = 4*l + j;
        int G = (rho >> 5)*Hz + slice*32 + (rho & 31);
        const float4* row = (const float4*)(Whh + (long long)G*Hz) + kw*8;
        #pragma unroll
        for (int k4 = 0; k4 < 8; k4++){
            float4 v = row[k4];
            wr[j][4*k4+0]=v.x; wr[j][4*k4+1]=v.y; wr[j][4*k4+2]=v.z; wr[j][4*k4+3]=v.w;
        }
    }
    int myG = 0;
    if (t < 128) myG = (t >> 5)*Hz + slice*32 + (t & 31);

    __shared__ float part[8][128];
    __shared__ float tsh[128];
    float c = 0.f, hlast = 0.f;

    for (int ts = 0; ts < Sz; ts++){
        int s = dir ? (Sz-1-ts) : ts;
        float prev = (t < 128) ? __ldg(&pre[(long long)s*H4z + myG]) : 0.f;
        const float* hb_r = g_hbuf + (long long)(ts & 1)*16*Hz + unit*Hz;
        float*       hb_w = g_hbuf + (long long)((ts+1) & 1)*16*Hz + unit*Hz;
        float hreg[32];
        const float4* hp = (const float4*)(hb_r) + kw*8;
        #pragma unroll
        for (int k4 = 0; k4 < 8; k4++){
            float4 v = __ldcg(hp + k4);
            hreg[4*k4+0]=v.x; hreg[4*k4+1]=v.y; hreg[4*k4+2]=v.z; hreg[4*k4+3]=v.w;
        }
        float acc0=0.f, acc1=0.f, acc2=0.f, acc3=0.f;
        #pragma unroll
        for (int k = 0; k < 32; k++){
            float hv = hreg[k];
            acc0 = fmaf(wr[0][k], hv, acc0);
            acc1 = fmaf(wr[1][k], hv, acc1);
            acc2 = fmaf(wr[2][k], hv, acc2);
            acc3 = fmaf(wr[3][k], hv, acc3);
        }
        part[kw][4*l+0]=acc0; part[kw][4*l+1]=acc1;
        part[kw][4*l+2]=acc2; part[kw][4*l+3]=acc3;
        __syncthreads();
        if (t < 128){
            float tot = prev;
            #pragma unroll
            for (int w2 = 0; w2 < 8; w2++) tot += part[w2][t];
            tsh[t] = tot;
        }
        __syncthreads();
        if (t < 32){
            float iv = sigmf_(tsh[t]);
            float fv = sigmf_(tsh[32+t]);
            float gv = tanhf(tsh[64+t]);
            float ov = sigmf_(tsh[96+t]);
            c = fv*c + iv*gv;
            float h = ov*tanhf(c);
            hlast = h;
            __stcg(&hb_w[slice*32 + t], h);
            if (!stage) hs[(long long)s*Hz + slice*32 + t] = h;
            if (ts < Sz-1){
                __threadfence();           // release our h stores
                __syncwarp();
                if (t == 0) __stcg(&g_flag[unit*8 + slice], ts+1);
                if (t < 8){                // parallel poll of the 8 slice flags
                    volatile int* vf = (volatile int*)&g_flag[unit*8 + t];
                    while (*vf <= ts) { }
                }
                __syncwarp();
                __threadfence();           // acquire peers' h stores
            }
        }
        if (ts < Sz-1) __syncthreads();    // releases block; orders next reads
    }
    if (stage && t < 32)
        g_s[OFF_HT + (long long)(grp*2+dir)*Bz*Hz + (long long)b*Hz + slice*32 + t] = hlast;
}

__global__ void norms_kernel(){
    int id = blockIdx.x;                 // 4*B*S
    int arr = id / (Bz*Sz), r = id % (Bz*Sz);
    int tid = threadIdx.x, w = tid >> 5, lane = tid & 31;
    __shared__ float sb[8];
    float x = g_s[OFF_HS + (long long)arr*BSH + (long long)r*Hz + tid];
    float s = warp_sum(x*x);
    if (lane == 0) sb[w] = s;
    __syncthreads();
    if (tid == 0){
        float tot = 0.f;
        #pragma unroll
        for (int i = 0; i < 8; i++) tot += sb[i];
        g_s[OFF_NRM + (long long)arr*Bz*Sz + r] = sqrtf(tot);
    }
}

// cosine attention + fused row max/sum
__global__ void att_kernel(){
    int id = blockIdx.x;                 // 2*B*S
    int dir = id / (Bz*Sz), r = id % (Bz*Sz);
    int b = r / Sz;
    __shared__ float v1s[Hz];
    __shared__ float sbs[8], sbm[8];
    int tid = threadIdx.x, w = tid >> 5, lane = tid & 31;
    v1s[tid] = g_s[OFF_HS + (long long)dir*BSH + (long long)r*Hz + tid];
    __syncthreads();
    const float4* v2 = (const float4*)(g_s + OFF_HS + (long long)(2+dir)*BSH + (long long)(b*Sz + tid)*Hz);
    float acc = 0.f;
    #pragma unroll 8
    for (int h4 = 0; h4 < Hz/4; h4++){
        float4 o = v2[h4];
        acc = fmaf(v1s[4*h4+0], o.x, acc);
        acc = fmaf(v1s[4*h4+1], o.y, acc);
        acc = fmaf(v1s[4*h4+2], o.z, acc);
        acc = fmaf(v1s[4*h4+3], o.w, acc);
    }
    float n1 = g_s[OFF_NRM + (long long)dir*Bz*Sz + r];
    float n2 = g_s[OFF_NRM + (long long)(2+dir)*Bz*Sz + b*Sz + tid];
    float d = n1*n2;
    float a = acc / (d > EPSf ? d : EPSf);
    g_s[OFF_ATT + (long long)dir*BSS + (long long)r*Sz + tid] = a;
    float ssum = warp_sum(a);
    float smax = warp_max(a);
    if (lane == 0){ sbs[w] = ssum; sbm[w] = smax; }
    __syncthreads();
    if (tid == 0){
        float tots = 0.f, totm = -3.4e38f;
        #pragma unroll
        for (int i = 0; i < 8; i++){ tots += sbs[i]; totm = fmaxf(totm, sbm[i]); }
        g_s[OFF_ROWSUM + (long long)dir*Bz*Sz + r] = tots;
        if (dir == 0){
            float* mp = g_s + OFF_MVP + (long long)r*AGGz;
            mp[0] = totm;
            mp[1] = tots / (float)Sz;
        }
    }
}

__global__ void colstats_kernel(){
    int dir = blockIdx.x / Bz, b = blockIdx.x % Bz;   // grid 2*B
    int q = threadIdx.x;
    const float* att = g_s + OFF_ATT + (long long)dir*BSS + (long long)b*Sz*Sz;
    float s = 0.f, m = -3.4e38f;
    for (int p = 0; p < Sz; p++){
        float a = att[(long long)p*Sz + q];
        s += a; m = fmaxf(m, a);
    }
    g_s[OFF_COLSUM + (long long)dir*Bz*Sz + b*Sz + q] = s;
    if (dir == 0){
        float* mh = g_s + OFF_MVH + (long long)(b*Sz + q)*AGGz;
        mh[0] = m;
        mh[1] = s / (float)Sz;
    }
}

// mean_h / max_h per (dir,b,p); tid = h
__global__ void statsrow_kernel(){
    int id = blockIdx.x;                 // 2*B*S
    int dir = id / (Bz*Sz), r = id % (Bz*Sz);
    int b = r / Sz;
    __shared__ float arow[Sz];
    int tid = threadIdx.x;
    arow[tid] = g_s[OFF_ATT + (long long)dir*BSS + (long long)r*Sz + tid];
    __syncthreads();
    const float* vh = g_s + OFF_HS + (long long)(2+dir)*BSH + (long long)b*Sz*Hz;
    float sm = 0.f, mx = -3.4e38f;
    for (int q = 0; q < Sz; q++){
        float pr = arow[q] * vh[(long long)q*Hz + tid];
        sm += pr; mx = fmaxf(mx, pr);
    }
    float rs = g_s[OFF_ROWSUM + (long long)dir*Bz*Sz + r];
    g_s[OFF_STATS + (long long)(0*2+dir)*BSH + (long long)r*Hz + tid] = sm / (rs > EPSf ? rs : EPSf);
    g_s[OFF_STATS + (long long)(1*2+dir)*BSH + (long long)r*Hz + tid] = mx;
}

// mean_p / max_p per (dir,b,q); tid = h
__global__ void statscol_kernel(){
    int id = blockIdx.x;                 // 2*B*S
    int dir = id / (Bz*Sz), r = id % (Bz*Sz);
    int b = r / Sz, q = r % Sz;
    __shared__ float acol[Sz];
    int tid = threadIdx.x;
    acol[tid] = g_s[OFF_ATT + (long long)dir*BSS + (long long)(b*Sz + tid)*Sz + q];
    __syncthreads();
    const float* vp = g_s + OFF_HS + (long long)dir*BSH + (long long)b*Sz*Hz;
    float sm = 0.f, mx = -3.4e38f;
    for (int p = 0; p < Sz; p++){
        float pr = acol[p] * vp[(long long)p*Hz + tid];
        sm += pr; mx = fmaxf(mx, pr);
    }
    float cs = g_s[OFF_COLSUM + (long long)dir*Bz*Sz + r];
    g_s[OFF_STATS + (long long)(2*2+dir)*BSH + (long long)r*Hz + tid] = sm / (cs > EPSf ? cs : EPSf);
    g_s[OFF_STATS + (long long)(3*2+dir)*BSH + (long long)r*Hz + tid] = mx;
}

// weighted norms: nlw[which][dir][b][s][l]
__global__ void normlw_kernel(const float* __restrict__ w3, const float* __restrict__ w4){
    int id = blockIdx.x;                 // 4*B*S
    int which = id / (2*Bz*Sz); int rem = id % (2*Bz*Sz);
    int dir = rem / (Bz*Sz), r = rem % (Bz*Sz);
    int arr = which ? (2+dir) : dir;
    const float* w = dir ? w4 : w3;
    __shared__ float red[Lz][8];
    int tid = threadIdx.x, wp = tid >> 5, lane = tid & 31;
    float x = g_s[OFF_HS + (long long)arr*BSH + (long long)r*Hz + tid];
    float vv = x*x;
    for (int l = 0; l < Lz; l++){
        float wv = __ldg(&w[l*Hz + tid]);
        float s = warp_sum(wv*wv*vv);
        if (lane == 0) red[l][wp] = s;
    }
    __syncthreads();
    if (tid < Lz){
        float s = 0.f;
        #pragma unroll
        for (int i = 0; i < 8; i++) s += red[tid][i];
        g_s[OFF_NLW + (long long)((which*2+dir)*Bz*Sz + r)*Lz + tid] = sqrtf(s);
    }
}

// pairwise matching + max reduce: pass0 fixed p -> mv_p, pass1 fixed q -> mv_h
__global__ void __launch_bounds__(256) pairwise_kernel(const float* __restrict__ w3, const float* __restrict__ w4){
    int id = blockIdx.x;                 // 4*B*S
    int pass = id / (2*Bz*Sz); int rem = id % (2*Bz*Sz);
    int dir = rem / (Bz*Sz), r = rem % (Bz*Sz);
    int b = r / Sz, s = r % Sz;
    const float* w = dir ? w4 : w3;
    __shared__ float w2s[Lz*Hz];
    __shared__ float vrow[Hz];
    __shared__ float red[Lz][8];
    int tid = threadIdx.x, wp = tid >> 5, lane = tid & 31;
    for (int i = tid; i < Lz*Hz; i += 256){ float x = w[i]; w2s[i] = x*x; }
    int rowArr = pass ? (2+dir) : dir;
    int colArr = pass ? dir : (2+dir);
    vrow[tid] = g_s[OFF_HS + (long long)rowArr*BSH + (long long)r*Hz + tid];
    __syncthreads();
    const float4* other = (const float4*)(g_s + OFF_HS + (long long)colArr*BSH + (long long)(b*Sz + tid)*Hz);
    float acc[Lz];
    #pragma unroll
    for (int l = 0; l < Lz; l++) acc[l] = 0.f;
    for (int h4 = 0; h4 < Hz/4; h4++){
        float4 o = other[h4];
        float p0 = vrow[4*h4+0]*o.x, p1 = vrow[4*h4+1]*o.y;
        float p2 = vrow[4*h4+2]*o.z, p3 = vrow[4*h4+3]*o.w;
        #pragma unroll
        for (int l = 0; l < Lz; l++){
            acc[l] = fmaf(w2s[l*Hz + 4*h4+0], p0, acc[l]);
            acc[l] = fmaf(w2s[l*Hz + 4*h4+1], p1, acc[l]);
            acc[l] = fmaf(w2s[l*Hz + 4*h4+2], p2, acc[l]);
            acc[l] = fmaf(w2s[l*Hz + 4*h4+3], p3, acc[l]);
        }
    }
    const float* nfix = g_s + OFF_NLW + (long long)(((pass?1:0)*2+dir)*Bz*Sz + b*Sz + s)*Lz;
    const float* nstr = g_s + OFF_NLW + (long long)(((pass?0:1)*2+dir)*Bz*Sz + b*Sz + tid)*Lz;
    #pragma unroll
    for (int l = 0; l < Lz; l++){
        float d = nfix[l]*nstr[l];
        float v = acc[l] / (d > EPSf ? d : EPSf);
        float m = warp_max(v);
        if (lane == 0) red[l][wp] = m;
    }
    __syncthreads();
    if (tid < Lz){
        float m = red[tid][0];
        #pragma unroll
        for (int i = 1; i < 8; i++) m = fmaxf(m, red[tid][i]);
        g_s[(pass ? OFF_MVH : OFF_MVP) + (long long)(b*Sz + s)*AGGz + 2 + dir*10 + tid] = m;
    }
}

// attentive / max-attentive mp_match, 8 combos
__global__ void mpmatch_kernel(const float* __restrict__ w5, const float* __restrict__ w6,
                               const float* __restrict__ w7, const float* __restrict__ w8){
    int id = blockIdx.x;                 // 8*B*S
    int k = id / (Bz*Sz), r = id % (Bz*Sz);
    int b = r / Sz, s = r % Sz;
    int dir = k & 1;
    int side = k >> 2;                   // 0: mv_p, 1: mv_h
    int arr  = side ? (2+dir) : dir;
    int kind = side ? ((k & 2) ? 3 : 2) : ((k & 2) ? 1 : 0);
    int wsel = k & 3;
    const float* w = (wsel==0) ? w5 : (wsel==1) ? w6 : (wsel==2) ? w7 : w8;
    __shared__ float rnum[Lz][8], rn1[Lz][8], rn2[Lz][8];
    int tid = threadIdx.x, wp = tid >> 5, lane = tid & 31;
    float a  = g_s[OFF_HS + (long long)arr*BSH + (long long)(b*Sz+s)*Hz + tid];
    float bb = g_s[OFF_STATS + (long long)(kind*2+dir)*BSH + (long long)(b*Sz+s)*Hz + tid];
    float ab = a*bb, aa = a*a, b2 = bb*bb;
    for (int l = 0; l < Lz; l++){
        float wv = __ldg(&w[l*Hz + tid]);
        float w2 = wv*wv;
        float num = warp_sum(w2*ab);
        float n1  = warp_sum(w2*aa);
        float n2  = warp_sum(w2*b2);
        if (lane == 0){ rnum[l][wp] = num; rn1[l][wp] = n1; rn2[l][wp] = n2; }
    }
    __syncthreads();
    if (tid < Lz){
        float N = 0.f, A = 0.f, B2 = 0.f;
        #pragma unroll
        for (int i = 0; i < 8; i++){ N += rnum[tid][i]; A += rn1[tid][i]; B2 += rn2[tid][i]; }
        g_s[(side ? OFF_MVH : OFF_MVP) + (long long)(b*Sz + s)*AGGz + 22 + wsel*10 + tid]
            = N / fmaxf(sqrtf(A)*sqrtf(B2), EPSf);
    }
}

__global__ void means_kernel(const float* __restrict__ left, const float* __restrict__ right){
    int which = blockIdx.x >> 2, b = blockIdx.x & 3;   // grid 8, 320 threads
    int d = threadIdx.x;
    if (d >= Dz) return;
    const float* x = which ? right : left;
    float s = 0.f;
    for (int t = 0; t < Sz; t++) s += x[((long long)b*Sz + t)*Dz + d];
    g_s[OFF_MEANS + (long long)which*Bz*Dz + (long long)b*Dz + d] = s / (float)Sz;
}

__global__ void fc1_kernel(const float* __restrict__ fc1_b){
    int b = blockIdx.x;                  // grid B, 512 threads
    int tid = threadIdx.x;
    __shared__ float feat[FEATN + 6];
    for (int i = tid; i < FEATN; i += 512){
        float v;
        if (i < 1024)       v = g_s[OFF_HT + (long long)(i >> 8)*Bz*Hz + (long long)b*Hz + (i & 255)];
        else if (i < 1026)  v = 0.5f;
        else if (i < 1326)  v = g_s[OFF_MEANS + (long long)b*Dz + (i - 1026)];
        else                v = g_s[OFF_MEANS + (long long)Bz*Dz + (long long)b*Dz + (i - 1326)];
        feat[i] = v;
    }
    __syncthreads();
    float acc = fc1_b[tid];
    for (int k = 0; k < FEATN; k++)
        acc = fmaf(feat[k], g_s[OFF_FC1WT + (long long)k*512 + tid], acc);
    g_s[OFF_FC1O + (long long)b*512 + tid] = tanhf(acc);
}

__global__ void fc2_kernel(const float* __restrict__ W2, const float* __restrict__ b2,
                           float* __restrict__ out){
    int b = blockIdx.x;                  // grid B, 512 threads
    int tid = threadIdx.x;
    __shared__ float y[512];
    y[tid] = g_s[OFF_FC1O + (long long)b*512 + tid];
    __syncthreads();
    if (tid < NCLSz){
        float acc = b2[tid];
        for (int o = 0; o < 512; o++) acc = fmaf(y[o], W2[(long long)tid*512 + o], acc);
        out[b*NCLSz + tid] = acc;
    }
}

extern "C" void kernel_launch(void* const* d_in, const int* in_sizes, int n_in,
                              void* d_out, int out_size){
    const float* left      = (const float*)d_in[0];
    const float* right     = (const float*)d_in[1];
    const float* ctx_Wih_f = (const float*)d_in[2];
    const float* ctx_Whh_f = (const float*)d_in[3];
    const float* ctx_b_f   = (const float*)d_in[4];
    const float* ctx_Wih_b = (const float*)d_in[5];
    const float* ctx_Whh_b = (const float*)d_in[6];
    const float* ctx_b_b   = (const float*)d_in[7];
    const float* agg_Wih_f = (const float*)d_in[8];
    const float* agg_Whh_f = (const float*)d_in[9];
    const float* agg_b_f   = (const float*)d_in[10];
    const float* agg_Wih_b = (const float*)d_in[11];
    const float* agg_Whh_b = (const float*)d_in[12];
    const float* agg_b_b   = (const float*)d_in[13];
    const float* mp_w3     = (const float*)d_in[14];
    const float* mp_w4     = (const float*)d_in[15];
    const float* mp_w5     = (const float*)d_in[16];
    const float* mp_w6     = (const float*)d_in[17];
    const float* mp_w7     = (const float*)d_in[18];
    const float* mp_w8     = (const float*)d_in[19];
    const float* fc1_W     = (const float*)d_in[20];
    const float* fc1_b     = (const float*)d_in[21];
    const float* fc2_W     = (const float*)d_in[22];
    const float* fc2_b     = (const float*)d_in[23];
    float* out = (float*)d_out;

    // weight transposes: 3 launches (so launch #6 = lstm2 for ncu -s 5 -c 1)
    transpose2_kernel<<<dim3(128,1,2),256>>>(ctx_Wih_f, ctx_Wih_b, OFF_WIHT_CF, OFF_WIHT_CB, H4z, Dz);
    transpose2_kernel<<<dim3(64,1,2),256>>>(agg_Wih_f, agg_Wih_b, OFF_WIHT_AF, OFF_WIHT_AB, H4z, AGGz);
    transpose_kernel<<<256,256>>>(fc1_W, OFF_FC1WT, 512, FEATN);

    // ctx pre-activation GEMMs, batched over z (left f/b, right f/b)
    gemm4_kernel<<<dim3(16,16,4),256>>>(left, right, 0, 0,
        OFF_WIHT_CF, (long long)Dz*H4z, ctx_b_f, ctx_b_b,
        OFF_PRE_CTX, Bz*Sz, H4z, Dz);

    zero_sync_kernel<<<1,256>>>();
    lstm2_kernel<<<128,256>>>(0, ctx_Whh_f, ctx_Whh_b);

    norms_kernel<<<4*Bz*Sz,256>>>();
    att_kernel<<<2*Bz*Sz,256>>>();
    colstats_kernel<<<2*Bz,256>>>();
    statsrow_kernel<<<2*Bz*Sz,256>>>();
    statscol_kernel<<<2*Bz*Sz,256>>>();
    normlw_kernel<<<4*Bz*Sz,256>>>(mp_w3, mp_w4);
    pairwise_kernel<<<4*Bz*Sz,256>>>(mp_w3, mp_w4);
    mpmatch_kernel<<<8*Bz*Sz,256>>>(mp_w5, mp_w6, mp_w7, mp_w8);
    means_kernel<<<8,320>>>(left, right);

    // agg pre-activation GEMMs, batched over z (mv_p f/b, mv_h f/b)
    gemm4_kernel<<<dim3(16,16,4),256>>>(nullptr, nullptr, OFF_MVP, OFF_MVH,
        OFF_WIHT_AF, (long long)AGGz*H4z, agg_b_f, agg_b_b,
        OFF_PRE_AGG, Bz*Sz, H4z, AGGz);

    zero_sync_kernel<<<1,256>>>();
    lstm2_kernel<<<128,256>>>(1, agg_Whh_f, agg_Whh_b);

    fc1_kernel<<<Bz,512>>>(fc1_b);
    fc2_kernel<<<Bz,512>>>(fc2_W, fc2_b, out);
}

// round 8
// speedup vs baseline: 1.4566x; 1.4566x over previous
#include <cuda_runtime.h>
#include <math.h>

// ---------------- problem constants ----------------
#define Bz   4
#define Sz   256
#define Dz   300
#define Hz   256
#define H4z  1024
#define Lz   10
#define AGGz 62
#define NCLSz 22
#define FEATN 1626          // 4*H + 2 + 2*D
#define BSH  (Bz*Sz*Hz)     // 262144
#define BSS  (Bz*Sz*Sz)     // 262144
#define EPSf 1e-8f

// ---------------- scratch layout (floats) ----------------
constexpr long long OFF_WIHT_CF = 0;
constexpr long long OFF_WIHT_CB = OFF_WIHT_CF + (long long)Dz*H4z;
constexpr long long OFF_WIHT_AF = OFF_WIHT_CB + (long long)Dz*H4z;
constexpr long long OFF_WIHT_AB = OFF_WIHT_AF + (long long)AGGz*H4z;
constexpr long long OFF_FC1WT   = OFF_WIHT_AB + (long long)AGGz*H4z;
constexpr long long OFF_PRE_CTX = OFF_FC1WT + (long long)FEATN*512;
constexpr long long OFF_HS      = OFF_PRE_CTX + 4LL*Bz*Sz*H4z;   // p_fw,p_bw,h_fw,h_bw
constexpr long long OFF_NRM     = OFF_HS + 4LL*BSH;              // (4,B,S)
constexpr long long OFF_ATT     = OFF_NRM + 4LL*Bz*Sz;           // (2,B,S,S)
constexpr long long OFF_ROWSUM  = OFF_ATT + 2LL*BSS;             // (2,B,S)
constexpr long long OFF_COLSUM  = OFF_ROWSUM + 2LL*Bz*Sz;        // (2,B,S)
constexpr long long OFF_STATS   = OFF_COLSUM + 2LL*Bz*Sz;        // (4 kinds x 2 dirs, B,S,H)
constexpr long long OFF_NLW     = OFF_STATS + 8LL*BSH;           // (2 which,2 dir,B,S,L)
constexpr long long OFF_MVP     = OFF_NLW + 4LL*Bz*Sz*Lz;        // (B,S,62)
constexpr long long OFF_MVH     = OFF_MVP + (long long)Bz*Sz*AGGz;
constexpr long long OFF_PRE_AGG = OFF_MVH + (long long)Bz*Sz*AGGz;
constexpr long long OFF_HT      = OFF_PRE_AGG + 4LL*Bz*Sz*H4z;   // (4,B,H)
constexpr long long OFF_MEANS   = OFF_HT + 4LL*Bz*Hz;            // (2,B,D)
constexpr long long OFF_FC1O    = OFF_MEANS + 2LL*Bz*Dz;         // (B,512)
constexpr long long SCRATCH_N   = OFF_FC1O + (long long)Bz*512 + 64;

__device__ __align__(256) float g_s[SCRATCH_N];

__device__ __forceinline__ float sigmf_(float x){ return 1.f/(1.f+expf(-x)); }

__device__ __forceinline__ float warp_sum(float v){
    #pragma unroll
    for (int o = 16; o > 0; o >>= 1) v += __shfl_down_sync(0xffffffffu, v, o);
    return v;
}
__device__ __forceinline__ float warp_max(float v){
    #pragma unroll
    for (int o = 16; o > 0; o >>= 1) v = fmaxf(v, __shfl_down_sync(0xffffffffu, v, o));
    return v;
}
__device__ __forceinline__ unsigned smem_u32(const void* p){
    unsigned r;
    asm("{ .reg .u64 t; cvta.to.shared.u64 t, %1; cvt.u32.u64 %0, t; }" : "=r"(r) : "l"(p));
    return r;
}

// two transposes in one launch: z selects (src, dst); src (R,C) -> g_s[dst] as (C,R)
__global__ void transpose2_kernel(const float* __restrict__ s0, const float* __restrict__ s1,
                                  long long d0, long long d1, int R, int C){
    const float* src = blockIdx.z ? s1 : s0;
    long long dst = blockIdx.z ? d1 : d0;
    long long total = (long long)R*C;
    for (long long i = blockIdx.x*(long long)blockDim.x + threadIdx.x; i < total;
         i += (long long)gridDim.x*blockDim.x){
        int r = (int)(i / C), c = (int)(i % C);
        g_s[dst + (long long)c*R + r] = src[i];
    }
}

// single transpose (fc1)
__global__ void transpose_kernel(const float* __restrict__ src, long long dst_off, int R, int C){
    long long total = (long long)R*C;
    for (long long i = blockIdx.x*(long long)blockDim.x + threadIdx.x; i < total;
         i += (long long)gridDim.x*blockDim.x){
        int r = (int)(i / C), c = (int)(i % C);
        g_s[dst_off + (long long)c*R + r] = src[i];
    }
}

// Batched GEMM over z=0..3: C_z(MxN) = A_z(MxK) * Bt_z(KxN) + bias_z(N)
__global__ void __launch_bounds__(256) gemm4_kernel(
        const float* __restrict__ A0, const float* __restrict__ A1,
        long long a0_off, long long a1_off,
        long long bt_base, long long bt_stride,
        const float* __restrict__ biasF, const float* __restrict__ biasB,
        long long c_off, int M, int N, int K){
    int z = blockIdx.z;
    const float* A  = (z < 2) ? (A0 ? A0 : (g_s + a0_off)) : (A1 ? A1 : (g_s + a1_off));
    const float* Bt = g_s + bt_base + (long long)(z & 1)*bt_stride;
    const float* bias = (z & 1) ? biasB : biasF;
    float* C = g_s + c_off + (long long)z*M*N;
    __shared__ float As[16][64];
    __shared__ float Bs[16][64];
    int bm = blockIdx.y*64, bn = blockIdx.x*64;
    int tid = threadIdx.x;
    int tr = tid >> 4, tc = tid & 15;
    float acc[4][4] = {};
    for (int k0 = 0; k0 < K; k0 += 16){
        for (int i = tid; i < 1024; i += 256){
            int m = i >> 4, k = i & 15;
            As[k][m] = (k0+k < K) ? A[(long long)(bm+m)*K + k0 + k] : 0.f;
        }
        for (int i = tid; i < 1024; i += 256){
            int k = i >> 6, n = i & 63;
            Bs[k][n] = (k0+k < K) ? Bt[(long long)(k0+k)*N + bn + n] : 0.f;
        }
        __syncthreads();
        #pragma unroll
        for (int k = 0; k < 16; k++){
            float a[4], bv[4];
            #pragma unroll
            for (int i = 0; i < 4; i++) a[i]  = As[k][tr*4+i];
            #pragma unroll
            for (int j = 0; j < 4; j++) bv[j] = Bs[k][tc*4+j];
            #pragma unroll
            for (int i = 0; i < 4; i++)
                #pragma unroll
                for (int j = 0; j < 4; j++) acc[i][j] = fmaf(a[i], bv[j], acc[i][j]);
        }
        __syncthreads();
    }
    #pragma unroll
    for (int i = 0; i < 4; i++){
        int m = bm + tr*4 + i;
        #pragma unroll
        for (int j = 0; j < 4; j++){
            int n = bn + tc*4 + j;
            C[(long long)m*N + n] = acc[i][j] + bias[n];
        }
    }
}

// Cluster LSTM: 8-CTA cluster per (input,dir,batch) unit; grid=128, 256 thr.
// Weights in registers (128 rows/block); h double-buffered in SMEM, broadcast
// to all 8 peers via DSMEM stores; step barrier = barrier.cluster.
__global__ void __cluster_dims__(8,1,1) __launch_bounds__(256,1) lstm3_kernel(int stage,
        const float* __restrict__ Whh_f, const float* __restrict__ Whh_b){
    int slice;
    asm("mov.u32 %0, %%cluster_ctarank;" : "=r"(slice));
    int unit = blockIdx.x >> 3;
    int grp = unit >> 3, dir = (unit >> 2) & 1, b = unit & 3;
    long long chunk = (long long)(grp*2 + dir)*Bz + b;
    const float* pre = g_s + (stage ? OFF_PRE_AGG : OFF_PRE_CTX) + chunk*(long long)Sz*H4z;
    const float* Whh = dir ? Whh_b : Whh_f;
    float* hs = g_s + OFF_HS + chunk*(long long)Sz*Hz;

    int t = threadIdx.x;
    int kw = t >> 5, l = t & 31;

    // weight tile -> registers: rows rho=4l..4l+3, k in [kw*32, kw*32+32)
    float wr[4][32];
    #pragma unroll
    for (int j = 0; j < 4; j++){
        int rho = 4*l + j;
        int G = (rho >> 5)*Hz + slice*32 + (rho & 31);
        const float4* row = (const float4*)(Whh + (long long)G*Hz) + kw*8;
        #pragma unroll
        for (int k4 = 0; k4 < 8; k4++){
            float4 v = row[k4];
            wr[j][4*k4+0]=v.x; wr[j][4*k4+1]=v.y; wr[j][4*k4+2]=v.z; wr[j][4*k4+3]=v.w;
        }
    }
    int myG = 0;
    if (t < 128) myG = (t >> 5)*Hz + slice*32 + (t & 31);

    __shared__ float hsm[2][Hz];     // double-buffered unit h (full 256)
    __shared__ float part[8][128];
    __shared__ float tsh[128];

    hsm[0][t] = 0.f;                 // zero read-buffer of step 0 only

    // precompute remote DSMEM base addresses of hsm for all 8 cluster ranks
    unsigned rbase[8];
    if (t < 32){
        unsigned lbase = smem_u32(&hsm[0][0]);
        #pragma unroll
        for (int rb = 0; rb < 8; rb++){
            asm("mapa.shared::cluster.u32 %0, %1, %2;"
                : "=r"(rbase[rb]) : "r"(lbase), "r"(rb));
        }
    }
    float c = 0.f, hlast = 0.f;
    __syncthreads();

    for (int ts = 0; ts < Sz; ts++){
        int s = dir ? (Sz-1-ts) : ts;
        float prev = (t < 128) ? __ldg(&pre[(long long)s*H4z + myG]) : 0.f;
        // local smem read of h (broadcast within warp)
        const float4* hp = (const float4*)(&hsm[ts & 1][0]) + kw*8;
        float hreg[32];
        #pragma unroll
        for (int k4 = 0; k4 < 8; k4++){
            float4 v = hp[k4];
            hreg[4*k4+0]=v.x; hreg[4*k4+1]=v.y; hreg[4*k4+2]=v.z; hreg[4*k4+3]=v.w;
        }
        float acc0=0.f, acc1=0.f, acc2=0.f, acc3=0.f;
        #pragma unroll
        for (int k = 0; k < 32; k++){
            float hv = hreg[k];
            acc0 = fmaf(wr[0][k], hv, acc0);
            acc1 = fmaf(wr[1][k], hv, acc1);
            acc2 = fmaf(wr[2][k], hv, acc2);
            acc3 = fmaf(wr[3][k], hv, acc3);
        }
        part[kw][4*l+0]=acc0; part[kw][4*l+1]=acc1;
        part[kw][4*l+2]=acc2; part[kw][4*l+3]=acc3;
        __syncthreads();
        if (t < 128){
            float tot = prev;
            #pragma unroll
            for (int w2 = 0; w2 < 8; w2++) tot += part[w2][t];
            tsh[t] = tot;
        }
        __syncthreads();
        if (t < 32){
            float iv = sigmf_(tsh[t]);
            float fv = sigmf_(tsh[32+t]);
            float gv = tanhf(tsh[64+t]);
            float ov = sigmf_(tsh[96+t]);
            c = fv*c + iv*gv;
            float h = ov*tanhf(c);
            hlast = h;
            if (!stage) hs[(long long)s*Hz + slice*32 + t] = h;
            if (ts < Sz-1){
                // broadcast h to hsm[(ts+1)&1][slice*32+t] in all 8 cluster CTAs
                unsigned off = (unsigned)(((ts+1) & 1)*Hz + slice*32 + t)*4u;
                unsigned hb = __float_as_uint(h);
                #pragma unroll
                for (int rb = 0; rb < 8; rb++){
                    asm volatile("st.shared::cluster.u32 [%0], %1;"
                                 :: "r"(rbase[rb] + off), "r"(hb) : "memory");
                }
            }
        }
        if (ts < Sz-1){
            // release (covers DSMEM stores) + acquire: lockstep across the cluster
            asm volatile("barrier.cluster.arrive.aligned;" ::: "memory");
            asm volatile("barrier.cluster.wait.aligned;" ::: "memory");
        }
    }
    if (stage && t < 32)
        g_s[OFF_HT + (long long)(grp*2+dir)*Bz*Hz + (long long)b*Hz + slice*32 + t] = hlast;
}

__global__ void norms_kernel(){
    int id = blockIdx.x;                 // 4*B*S
    int arr = id / (Bz*Sz), r = id % (Bz*Sz);
    int tid = threadIdx.x, w = tid >> 5, lane = tid & 31;
    __shared__ float sb[8];
    float x = g_s[OFF_HS + (long long)arr*BSH + (long long)r*Hz + tid];
    float s = warp_sum(x*x);
    if (lane == 0) sb[w] = s;
    __syncthreads();
    if (tid == 0){
        float tot = 0.f;
        #pragma unroll
        for (int i = 0; i < 8; i++) tot += sb[i];
        g_s[OFF_NRM + (long long)arr*Bz*Sz + r] = sqrtf(tot);
    }
}

// cosine attention + fused row max/sum
__global__ void att_kernel(){
    int id = blockIdx.x;                 // 2*B*S
    int dir = id / (Bz*Sz), r = id % (Bz*Sz);
    int b = r / Sz;
    __shared__ float v1s[Hz];
    __shared__ float sbs[8], sbm[8];
    int tid = threadIdx.x, w = tid >> 5, lane = tid & 31;
    v1s[tid] = g_s[OFF_HS + (long long)dir*BSH + (long long)r*Hz + tid];
    __syncthreads();
    const float4* v2 = (const float4*)(g_s + OFF_HS + (long long)(2+dir)*BSH + (long long)(b*Sz + tid)*Hz);
    float acc = 0.f;
    #pragma unroll 8
    for (int h4 = 0; h4 < Hz/4; h4++){
        float4 o = v2[h4];
        acc = fmaf(v1s[4*h4+0], o.x, acc);
        acc = fmaf(v1s[4*h4+1], o.y, acc);
        acc = fmaf(v1s[4*h4+2], o.z, acc);
        acc = fmaf(v1s[4*h4+3], o.w, acc);
    }
    float n1 = g_s[OFF_NRM + (long long)dir*Bz*Sz + r];
    float n2 = g_s[OFF_NRM + (long long)(2+dir)*Bz*Sz + b*Sz + tid];
    float d = n1*n2;
    float a = acc / (d > EPSf ? d : EPSf);
    g_s[OFF_ATT + (long long)dir*BSS + (long long)r*Sz + tid] = a;
    float ssum = warp_sum(a);
    float smax = warp_max(a);
    if (lane == 0){ sbs[w] = ssum; sbm[w] = smax; }
    __syncthreads();
    if (tid == 0){
        float tots = 0.f, totm = -3.4e38f;
        #pragma unroll
        for (int i = 0; i < 8; i++){ tots += sbs[i]; totm = fmaxf(totm, sbm[i]); }
        g_s[OFF_ROWSUM + (long long)dir*Bz*Sz + r] = tots;
        if (dir == 0){
            float* mp = g_s + OFF_MVP + (long long)r*AGGz;
            mp[0] = totm;
            mp[1] = tots / (float)Sz;
        }
    }
}

__global__ void colstats_kernel(){
    int dir = blockIdx.x / Bz, b = blockIdx.x % Bz;   // grid 2*B
    int q = threadIdx.x;
    const float* att = g_s + OFF_ATT + (long long)dir*BSS + (long long)b*Sz*Sz;
    float s = 0.f, m = -3.4e38f;
    for (int p = 0; p < Sz; p++){
        float a = att[(long long)p*Sz + q];
        s += a; m = fmaxf(m, a);
    }
    g_s[OFF_COLSUM + (long long)dir*Bz*Sz + b*Sz + q] = s;
    if (dir == 0){
        float* mh = g_s + OFF_MVH + (long long)(b*Sz + q)*AGGz;
        mh[0] = m;
        mh[1] = s / (float)Sz;
    }
}

// mean_h / max_h per (dir,b,p); tid = h
__global__ void statsrow_kernel(){
    int id = blockIdx.x;                 // 2*B*S
    int dir = id / (Bz*Sz), r = id % (Bz*Sz);
    int b = r / Sz;
    __shared__ float arow[Sz];
    int tid = threadIdx.x;
    arow[tid] = g_s[OFF_ATT + (long long)dir*BSS + (long long)r*Sz + tid];
    __syncthreads();
    const float* vh = g_s + OFF_HS + (long long)(2+dir)*BSH + (long long)b*Sz*Hz;
    float sm = 0.f, mx = -3.4e38f;
    for (int q = 0; q < Sz; q++){
        float pr = arow[q] * vh[(long long)q*Hz + tid];
        sm += pr; mx = fmaxf(mx, pr);
    }
    float rs = g_s[OFF_ROWSUM + (long long)dir*Bz*Sz + r];
    g_s[OFF_STATS + (long long)(0*2+dir)*BSH + (long long)r*Hz + tid] = sm / (rs > EPSf ? rs : EPSf);
    g_s[OFF_STATS + (long long)(1*2+dir)*BSH + (long long)r*Hz + tid] = mx;
}

// mean_p / max_p per (dir,b,q); tid = h
__global__ void statscol_kernel(){
    int id = blockIdx.x;                 // 2*B*S
    int dir = id / (Bz*Sz), r = id % (Bz*Sz);
    int b = r / Sz, q = r % Sz;
    __shared__ float acol[Sz];
    int tid = threadIdx.x;
    acol[tid] = g_s[OFF_ATT + (long long)dir*BSS + (long long)(b*Sz + tid)*Sz + q];
    __syncthreads();
    const float* vp = g_s + OFF_HS + (long long)dir*BSH + (long long)b*Sz*Hz;
    float sm = 0.f, mx = -3.4e38f;
    for (int p = 0; p < Sz; p++){
        float pr = acol[p] * vp[(long long)p*Hz + tid];
        sm += pr; mx = fmaxf(mx, pr);
    }
    float cs = g_s[OFF_COLSUM + (long long)dir*Bz*Sz + r];
    g_s[OFF_STATS + (long long)(2*2+dir)*BSH + (long long)r*Hz + tid] = sm / (cs > EPSf ? cs : EPSf);
    g_s[OFF_STATS + (long long)(3*2+dir)*BSH + (long long)r*Hz + tid] = mx;
}

// weighted norms: nlw[which][dir][b][s][l]
__global__ void normlw_kernel(const float* __restrict__ w3, const float* __restrict__ w4){
    int id = blockIdx.x;                 // 4*B*S
    int which = id / (2*Bz*Sz); int rem = id % (2*Bz*Sz);
    int dir = rem / (Bz*Sz), r = rem % (Bz*Sz);
    int arr = which ? (2+dir) : dir;
    const float* w = dir ? w4 : w3;
    __shared__ float red[Lz][8];
    int tid = threadIdx.x, wp = tid >> 5, lane = tid & 31;
    float x = g_s[OFF_HS + (long long)arr*BSH + (long long)r*Hz + tid];
    float vv = x*x;
    for (int l = 0; l < Lz; l++){
        float wv = __ldg(&w[l*Hz + tid]);
        float s = warp_sum(wv*wv*vv);
        if (lane == 0) red[l][wp] = s;
    }
    __syncthreads();
    if (tid < Lz){
        float s = 0.f;
        #pragma unroll
        for (int i = 0; i < 8; i++) s += red[tid][i];
        g_s[OFF_NLW + (long long)((which*2+dir)*Bz*Sz + r)*Lz + tid] = sqrtf(s);
    }
}

// pairwise matching + max reduce: pass0 fixed p -> mv_p, pass1 fixed q -> mv_h
__global__ void __launch_bounds__(256) pairwise_kernel(const float* __restrict__ w3, const float* __restrict__ w4){
    int id = blockIdx.x;                 // 4*B*S
    int pass = id / (2*Bz*Sz); int rem = id % (2*Bz*Sz);
    int dir = rem / (Bz*Sz), r = rem % (Bz*Sz);
    int b = r / Sz, s = r % Sz;
    const float* w = dir ? w4 : w3;
    __shared__ float w2s[Lz*Hz];
    __shared__ float vrow[Hz];
    __shared__ float red[Lz][8];
    int tid = threadIdx.x, wp = tid >> 5, lane = tid & 31;
    for (int i = tid; i < Lz*Hz; i += 256){ float x = w[i]; w2s[i] = x*x; }
    int rowArr = pass ? (2+dir) : dir;
    int colArr = pass ? dir : (2+dir);
    vrow[tid] = g_s[OFF_HS + (long long)rowArr*BSH + (long long)r*Hz + tid];
    __syncthreads();
    const float4* other = (const float4*)(g_s + OFF_HS + (long long)colArr*BSH + (long long)(b*Sz + tid)*Hz);
    float acc[Lz];
    #pragma unroll
    for (int l = 0; l < Lz; l++) acc[l] = 0.f;
    for (int h4 = 0; h4 < Hz/4; h4++){
        float4 o = other[h4];
        float p0 = vrow[4*h4+0]*o.x, p1 = vrow[4*h4+1]*o.y;
        float p2 = vrow[4*h4+2]*o.z, p3 = vrow[4*h4+3]*o.w;
        #pragma unroll
        for (int l = 0; l < Lz; l++){
            acc[l] = fmaf(w2s[l*Hz + 4*h4+0], p0, acc[l]);
            acc[l] = fmaf(w2s[l*Hz + 4*h4+1], p1, acc[l]);
            acc[l] = fmaf(w2s[l*Hz + 4*h4+2], p2, acc[l]);
            acc[l] = fmaf(w2s[l*Hz + 4*h4+3], p3, acc[l]);
        }
    }
    const float* nfix = g_s + OFF_NLW + (long long)(((pass?1:0)*2+dir)*Bz*Sz + b*Sz + s)*Lz;
    const float* nstr = g_s + OFF_NLW + (long long)(((pass?0:1)*2+dir)*Bz*Sz + b*Sz + tid)*Lz;
    #pragma unroll
    for (int l = 0; l < Lz; l++){
        float d = nfix[l]*nstr[l];
        float v = acc[l] / (d > EPSf ? d : EPSf);
        float m = warp_max(v);
        if (lane == 0) red[l][wp] = m;
    }
    __syncthreads();
    if (tid < Lz){
        float m = red[tid][0];
        #pragma unroll
        for (int i = 1; i < 8; i++) m = fmaxf(m, red[tid][i]);
        g_s[(pass ? OFF_MVH : OFF_MVP) + (long long)(b*Sz + s)*AGGz + 2 + dir*10 + tid] = m;
    }
}

// attentive / max-attentive mp_match, 8 combos
__global__ void mpmatch_kernel(const float* __restrict__ w5, const float* __restrict__ w6,
                               const float* __restrict__ w7, const float* __restrict__ w8){
    int id = blockIdx.x;                 // 8*B*S
    int k = id / (Bz*Sz), r = id % (Bz*Sz);
    int b = r / Sz, s = r % Sz;
    int dir = k & 1;
    int side = k >> 2;                   // 0: mv_p, 1: mv_h
    int arr  = side ? (2+dir) : dir;
    int kind = side ? ((k & 2) ? 3 : 2) : ((k & 2) ? 1 : 0);
    int wsel = k & 3;
    const float* w = (wsel==0) ? w5 : (wsel==1) ? w6 : (wsel==2) ? w7 : w8;
    __shared__ float rnum[Lz][8], rn1[Lz][8], rn2[Lz][8];
    int tid = threadIdx.x, wp = tid >> 5, lane = tid & 31;
    float a  = g_s[OFF_HS + (long long)arr*BSH + (long long)(b*Sz+s)*Hz + tid];
    float bb = g_s[OFF_STATS + (long long)(kind*2+dir)*BSH + (long long)(b*Sz+s)*Hz + tid];
    float ab = a*bb, aa = a*a, b2 = bb*bb;
    for (int l = 0; l < Lz; l++){
        float wv = __ldg(&w[l*Hz + tid]);
        float w2 = wv*wv;
        float num = warp_sum(w2*ab);
        float n1  = warp_sum(w2*aa);
        float n2  = warp_sum(w2*b2);
        if (lane == 0){ rnum[l][wp] = num; rn1[l][wp] = n1; rn2[l][wp] = n2; }
    }
    __syncthreads();
    if (tid < Lz){
        float N = 0.f, A = 0.f, B2 = 0.f;
        #pragma unroll
        for (int i = 0; i < 8; i++){ N += rnum[tid][i]; A += rn1[tid][i]; B2 += rn2[tid][i]; }
        g_s[(side ? OFF_MVH : OFF_MVP) + (long long)(b*Sz + s)*AGGz + 22 + wsel*10 + tid]
            = N / fmaxf(sqrtf(A)*sqrtf(B2), EPSf);
    }
}

__global__ void means_kernel(const float* __restrict__ left, const float* __restrict__ right){
    int which = blockIdx.x >> 2, b = blockIdx.x & 3;   // grid 8, 320 threads
    int d = threadIdx.x;
    if (d >= Dz) return;
    const float* x = which ? right : left;
    float s = 0.f;
    for (int t = 0; t < Sz; t++) s += x[((long long)b*Sz + t)*Dz + d];
    g_s[OFF_MEANS + (long long)which*Bz*Dz + (long long)b*Dz + d] = s / (float)Sz;
}

__global__ void fc1_kernel(const float* __restrict__ fc1_b){
    int b = blockIdx.x;                  // grid B, 512 threads
    int tid = threadIdx.x;
    __shared__ float feat[FEATN + 6];
    for (int i = tid; i < FEATN; i += 512){
        float v;
        if (i < 1024)       v = g_s[OFF_HT + (long long)(i >> 8)*Bz*Hz + (long long)b*Hz + (i & 255)];
        else if (i < 1026)  v = 0.5f;
        else if (i < 1326)  v = g_s[OFF_MEANS + (long long)b*Dz + (i - 1026)];
        else                v = g_s[OFF_MEANS + (long long)Bz*Dz + (long long)b*Dz + (i - 1326)];
        feat[i] = v;
    }
    __syncthreads();
    float acc = fc1_b[tid];
    for (int k = 0; k < FEATN; k++)
        acc = fmaf(feat[k], g_s[OFF_FC1WT + (long long)k*512 + tid], acc);
    g_s[OFF_FC1O + (long long)b*512 + tid] = tanhf(acc);
}

__global__ void fc2_kernel(const float* __restrict__ W2, const float* __restrict__ b2,
                           float* __restrict__ out){
    int b = blockIdx.x;                  // grid B, 512 threads
    int tid = threadIdx.x;
    __shared__ float y[512];
    y[tid] = g_s[OFF_FC1O + (long long)b*512 + tid];
    __syncthreads();
    if (tid < NCLSz){
        float acc = b2[tid];
        for (int o = 0; o < 512; o++) acc = fmaf(y[o], W2[(long long)tid*512 + o], acc);
        out[b*NCLSz + tid] = acc;
    }
}

extern "C" void kernel_launch(void* const* d_in, const int* in_sizes, int n_in,
                              void* d_out, int out_size){
    const float* left      = (const float*)d_in[0];
    const float* right     = (const float*)d_in[1];
    const float* ctx_Wih_f = (const float*)d_in[2];
    const float* ctx_Whh_f = (const float*)d_in[3];
    const float* ctx_b_f   = (const float*)d_in[4];
    const float* ctx_Wih_b = (const float*)d_in[5];
    const float* ctx_Whh_b = (const float*)d_in[6];
    const float* ctx_b_b   = (const float*)d_in[7];
    const float* agg_Wih_f = (const float*)d_in[8];
    const float* agg_Whh_f = (const float*)d_in[9];
    const float* agg_b_f   = (const float*)d_in[10];
    const float* agg_Wih_b = (const float*)d_in[11];
    const float* agg_Whh_b = (const float*)d_in[12];
    const float* agg_b_b   = (const float*)d_in[13];
    const float* mp_w3     = (const float*)d_in[14];
    const float* mp_w4     = (const float*)d_in[15];
    const float* mp_w5     = (const float*)d_in[16];
    const float* mp_w6     = (const float*)d_in[17];
    const float* mp_w7     = (const float*)d_in[18];
    const float* mp_w8     = (const float*)d_in[19];
    const float* fc1_W     = (const float*)d_in[20];
    const float* fc1_b     = (const float*)d_in[21];
    const float* fc2_W     = (const float*)d_in[22];
    const float* fc2_b     = (const float*)d_in[23];
    float* out = (float*)d_out;

    // weight transposes (Wih + fc1)
    transpose2_kernel<<<dim3(128,1,2),256>>>(ctx_Wih_f, ctx_Wih_b, OFF_WIHT_CF, OFF_WIHT_CB, H4z, Dz);
    transpose2_kernel<<<dim3(64,1,2),256>>>(agg_Wih_f, agg_Wih_b, OFF_WIHT_AF, OFF_WIHT_AB, H4z, AGGz);
    transpose_kernel<<<256,256>>>(fc1_W, OFF_FC1WT, 512, FEATN);

    // ctx pre-activation GEMMs, batched over z (left f/b, right f/b)
    gemm4_kernel<<<dim3(16,16,4),256>>>(left, right, 0, 0,
        OFF_WIHT_CF, (long long)Dz*H4z, ctx_b_f, ctx_b_b,
        OFF_PRE_CTX, Bz*Sz, H4z, Dz);

    lstm3_kernel<<<128,256>>>(0, ctx_Whh_f, ctx_Whh_b);

    norms_kernel<<<4*Bz*Sz,256>>>();
    att_kernel<<<2*Bz*Sz,256>>>();
    colstats_kernel<<<2*Bz,256>>>();
    statsrow_kernel<<<2*Bz*Sz,256>>>();
    statscol_kernel<<<2*Bz*Sz,256>>>();
    normlw_kernel<<<4*Bz*Sz,256>>>(mp_w3, mp_w4);
    pairwise_kernel<<<4*Bz*Sz,256>>>(mp_w3, mp_w4);
    mpmatch_kernel<<<8*Bz*Sz,256>>>(mp_w5, mp_w6, mp_w7, mp_w8);
    means_kernel<<<8,320>>>(left, right);

    // agg pre-activation GEMMs, batched over z (mv_p f/b, mv_h f/b)
    gemm4_kernel<<<dim3(16,16,4),256>>>(nullptr, nullptr, OFF_MVP, OFF_MVH,
        OFF_WIHT_AF, (long long)AGGz*H4z, agg_b_f, agg_b_b,
        OFF_PRE_AGG, Bz*Sz, H4z, AGGz);

    lstm3_kernel<<<128,256>>>(1, agg_Whh_f, agg_Whh_b);

    fc1_kernel<<<Bz,512>>>(fc1_b);
    fc2_kernel<<<Bz,512>>>(fc2_W, fc2_b, out);
}

// round 9
// speedup vs baseline: 1.6744x; 1.1496x over previous
#include <cuda_runtime.h>
#include <math.h>

// ---------------- problem constants ----------------
#define Bz   4
#define Sz   256
#define Dz   300
#define Hz   256
#define H4z  1024
#define Lz   10
#define AGGz 62
#define NCLSz 22
#define FEATN 1626          // 4*H + 2 + 2*D
#define BSH  (Bz*Sz*Hz)     // 262144
#define BSS  (Bz*Sz*Sz)     // 262144
#define EPSf 1e-8f

// ---------------- scratch layout (floats) ----------------
constexpr long long OFF_WIHT_CF = 0;
constexpr long long OFF_WIHT_CB = OFF_WIHT_CF + (long long)Dz*H4z;
constexpr long long OFF_WIHT_AF = OFF_WIHT_CB + (long long)Dz*H4z;
constexpr long long OFF_WIHT_AB = OFF_WIHT_AF + (long long)AGGz*H4z;
constexpr long long OFF_FC1WT   = OFF_WIHT_AB + (long long)AGGz*H4z;
constexpr long long OFF_PRE_CTX = OFF_FC1WT + (long long)FEATN*512;
constexpr long long OFF_HS      = OFF_PRE_CTX + 4LL*Bz*Sz*H4z;   // p_fw,p_bw,h_fw,h_bw
constexpr long long OFF_NRM     = OFF_HS + 4LL*BSH;              // (4,B,S)
constexpr long long OFF_ATT     = OFF_NRM + 4LL*Bz*Sz;           // (2,B,S,S)
constexpr long long OFF_ROWSUM  = OFF_ATT + 2LL*BSS;             // (2,B,S)
constexpr long long OFF_COLSUM  = OFF_ROWSUM + 2LL*Bz*Sz;        // (2,B,S)
constexpr long long OFF_STATS   = OFF_COLSUM + 2LL*Bz*Sz;        // (4 kinds x 2 dirs, B,S,H)
constexpr long long OFF_NLW     = OFF_STATS + 8LL*BSH;           // (arr, B,S,L)
constexpr long long OFF_MVP     = OFF_NLW + 4LL*Bz*Sz*Lz;        // (B,S,62)
constexpr long long OFF_MVH     = OFF_MVP + (long long)Bz*Sz*AGGz;
constexpr long long OFF_PRE_AGG = OFF_MVH + (long long)Bz*Sz*AGGz;
constexpr long long OFF_HT      = OFF_PRE_AGG + 4LL*Bz*Sz*H4z;   // (4,B,H)
constexpr long long OFF_MEANS   = OFF_HT + 4LL*Bz*Hz;            // (2,B,D)
constexpr long long OFF_FC1O    = OFF_MEANS + 2LL*Bz*Dz;         // (B,512)
constexpr long long OFF_MMS     = OFF_FC1O + (long long)Bz*512;  // (2,B,L,P,Q) mm spill
constexpr long long SCRATCH_N   = OFF_MMS + 2LL*Bz*Lz*Sz*Sz + 64;

__device__ __align__(256) float g_s[SCRATCH_N];

__device__ __forceinline__ float sigmf_(float x){ return 1.f/(1.f+expf(-x)); }

__device__ __forceinline__ float warp_sum(float v){
    #pragma unroll
    for (int o = 16; o > 0; o >>= 1) v += __shfl_down_sync(0xffffffffu, v, o);
    return v;
}
__device__ __forceinline__ float warp_max(float v){
    #pragma unroll
    for (int o = 16; o > 0; o >>= 1) v = fmaxf(v, __shfl_down_sync(0xffffffffu, v, o));
    return v;
}
__device__ __forceinline__ unsigned smem_u32(const void* p){
    unsigned r;
    asm("{ .reg .u64 t; cvta.to.shared.u64 t, %1; cvt.u32.u64 %0, t; }" : "=r"(r) : "l"(p));
    return r;
}

// two transposes in one launch: z selects (src, dst); src (R,C) -> g_s[dst] as (C,R)
__global__ void transpose2_kernel(const float* __restrict__ s0, const float* __restrict__ s1,
                                  long long d0, long long d1, int R, int C){
    const float* src = blockIdx.z ? s1 : s0;
    long long dst = blockIdx.z ? d1 : d0;
    long long total = (long long)R*C;
    for (long long i = blockIdx.x*(long long)blockDim.x + threadIdx.x; i < total;
         i += (long long)gridDim.x*blockDim.x){
        int r = (int)(i / C), c = (int)(i % C);
        g_s[dst + (long long)c*R + r] = src[i];
    }
}

// single transpose (fc1)
__global__ void transpose_kernel(const float* __restrict__ src, long long dst_off, int R, int C){
    long long total = (long long)R*C;
    for (long long i = blockIdx.x*(long long)blockDim.x + threadIdx.x; i < total;
         i += (long long)gridDim.x*blockDim.x){
        int r = (int)(i / C), c = (int)(i % C);
        g_s[dst_off + (long long)c*R + r] = src[i];
    }
}

// Batched GEMM over z=0..3: C_z(MxN) = A_z(MxK) * Bt_z(KxN) + bias_z(N)
// smem padded to 68 (bank-conflict fix) + float4 LDS in the MMA loop.
__global__ void __launch_bounds__(256) gemm4_kernel(
        const float* __restrict__ A0, const float* __restrict__ A1,
        long long a0_off, long long a1_off,
        long long bt_base, long long bt_stride,
        const float* __restrict__ biasF, const float* __restrict__ biasB,
        long long c_off, int M, int N, int K){
    int z = blockIdx.z;
    const float* A  = (z < 2) ? (A0 ? A0 : (g_s + a0_off)) : (A1 ? A1 : (g_s + a1_off));
    const float* Bt = g_s + bt_base + (long long)(z & 1)*bt_stride;
    const float* bias = (z & 1) ? biasB : biasF;
    float* C = g_s + c_off + (long long)z*M*N;
    __shared__ float As[16][68];
    __shared__ float Bs[16][68];
    int bm = blockIdx.y*64, bn = blockIdx.x*64;
    int tid = threadIdx.x;
    int tr = tid >> 4, tc = tid & 15;
    float acc[4][4] = {};
    for (int k0 = 0; k0 < K; k0 += 16){
        #pragma unroll
        for (int i = tid; i < 1024; i += 256){
            int m = i >> 4, k = i & 15;
            As[k][m] = (k0+k < K) ? A[(long long)(bm+m)*K + k0 + k] : 0.f;
        }
        #pragma unroll
        for (int i = tid; i < 1024; i += 256){
            int k = i >> 6, n = i & 63;
            Bs[k][n] = (k0+k < K) ? Bt[(long long)(k0+k)*N + bn + n] : 0.f;
        }
        __syncthreads();
        #pragma unroll
        for (int k = 0; k < 16; k++){
            float4 av = *(const float4*)&As[k][tr*4];
            float4 bv = *(const float4*)&Bs[k][tc*4];
            float a[4] = {av.x, av.y, av.z, av.w};
            float bb[4] = {bv.x, bv.y, bv.z, bv.w};
            #pragma unroll
            for (int i = 0; i < 4; i++)
                #pragma unroll
                for (int j = 0; j < 4; j++) acc[i][j] = fmaf(a[i], bb[j], acc[i][j]);
        }
        __syncthreads();
    }
    #pragma unroll
    for (int i = 0; i < 4; i++){
        int m = bm + tr*4 + i;
        #pragma unroll
        for (int j = 0; j < 4; j++){
            int n = bn + tc*4 + j;
            C[(long long)m*N + n] = acc[i][j] + bias[n];
        }
    }
}

// Cluster LSTM: 8-CTA cluster per (input,dir,batch) unit; grid=128, 256 thr.
// Weights in registers; h double-buffered in SMEM, DSMEM-broadcast to peers;
// step barrier = barrier.cluster. Cell warp sums partials directly (no tsh).
__global__ void __cluster_dims__(8,1,1) __launch_bounds__(256,1) lstm3_kernel(int stage,
        const float* __restrict__ Whh_f, const float* __restrict__ Whh_b){
    int slice;
    asm("mov.u32 %0, %%cluster_ctarank;" : "=r"(slice));
    int unit = blockIdx.x >> 3;
    int grp = unit >> 3, dir = (unit >> 2) & 1, b = unit & 3;
    long long chunk = (long long)(grp*2 + dir)*Bz + b;
    const float* pre = g_s + (stage ? OFF_PRE_AGG : OFF_PRE_CTX) + chunk*(long long)Sz*H4z;
    const float* Whh = dir ? Whh_b : Whh_f;
    float* hs = g_s + OFF_HS + chunk*(long long)Sz*Hz;

    int t = threadIdx.x;
    int kw = t >> 5, l = t & 31;

    // weight tile -> registers: rows rho=4l..4l+3, k in [kw*32, kw*32+32)
    float wr[4][32];
    #pragma unroll
    for (int j = 0; j < 4; j++){
        int rho = 4*l + j;
        int G = (rho >> 5)*Hz + slice*32 + (rho & 31);
        const float4* row = (const float4*)(Whh + (long long)G*Hz) + kw*8;
        #pragma unroll
        for (int k4 = 0; k4 < 8; k4++){
            float4 v = row[k4];
            wr[j][4*k4+0]=v.x; wr[j][4*k4+1]=v.y; wr[j][4*k4+2]=v.z; wr[j][4*k4+3]=v.w;
        }
    }

    __shared__ float hsm[2][Hz];     // double-buffered unit h (full 256)
    __shared__ float part[8][128];

    hsm[0][t] = 0.f;                 // zero read-buffer of step 0

    // remote DSMEM base addresses of hsm for all 8 cluster ranks
    unsigned rbase[8];
    if (t < 32){
        unsigned lbase = smem_u32(&hsm[0][0]);
        #pragma unroll
        for (int rb = 0; rb < 8; rb++){
            asm("mapa.shared::cluster.u32 %0, %1, %2;"
                : "=r"(rbase[rb]) : "r"(lbase), "r"(rb));
        }
    }
    float c = 0.f, hlast = 0.f;
    __syncthreads();

    for (int ts = 0; ts < Sz; ts++){
        int s = dir ? (Sz-1-ts) : ts;
        float prev0=0.f, prev1=0.f, prev2=0.f, prev3=0.f;
        if (t < 32){
            long long base = (long long)s*H4z + slice*32 + t;
            prev0 = __ldg(&pre[base + 0*Hz]);
            prev1 = __ldg(&pre[base + 1*Hz]);
            prev2 = __ldg(&pre[base + 2*Hz]);
            prev3 = __ldg(&pre[base + 3*Hz]);
        }
        const float4* hp = (const float4*)(&hsm[ts & 1][0]) + kw*8;
        float hreg[32];
        #pragma unroll
        for (int k4 = 0; k4 < 8; k4++){
            float4 v = hp[k4];
            hreg[4*k4+0]=v.x; hreg[4*k4+1]=v.y; hreg[4*k4+2]=v.z; hreg[4*k4+3]=v.w;
        }
        float acc0=0.f, acc1=0.f, acc2=0.f, acc3=0.f;
        #pragma unroll
        for (int k = 0; k < 32; k++){
            float hv = hreg[k];
            acc0 = fmaf(wr[0][k], hv, acc0);
            acc1 = fmaf(wr[1][k], hv, acc1);
            acc2 = fmaf(wr[2][k], hv, acc2);
            acc3 = fmaf(wr[3][k], hv, acc3);
        }
        part[kw][4*l+0]=acc0; part[kw][4*l+1]=acc1;
        part[kw][4*l+2]=acc2; part[kw][4*l+3]=acc3;
        __syncthreads();
        if (t < 32){
            float t0=prev0, t1=prev1, t2=prev2, t3=prev3;
            #pragma unroll
            for (int w2 = 0; w2 < 8; w2++){
                t0 += part[w2][t];
                t1 += part[w2][32+t];
                t2 += part[w2][64+t];
                t3 += part[w2][96+t];
            }
            float iv = sigmf_(t0);
            float fv = sigmf_(t1);
            float gv = tanhf(t2);
            float ov = sigmf_(t3);
            c = fv*c + iv*gv;
            float h = ov*tanhf(c);
            hlast = h;
            if (!stage) hs[(long long)s*Hz + slice*32 + t] = h;
            if (ts < Sz-1){
                unsigned off = (unsigned)(((ts+1) & 1)*Hz + slice*32 + t)*4u;
                unsigned hb = __float_as_uint(h);
                #pragma unroll
                for (int rb = 0; rb < 8; rb++){
                    asm volatile("st.shared::cluster.u32 [%0], %1;"
                                 :: "r"(rbase[rb] + off), "r"(hb) : "memory");
                }
            }
        }
        if (ts < Sz-1){
            asm volatile("barrier.cluster.arrive.aligned;" ::: "memory");
            asm volatile("barrier.cluster.wait.aligned;" ::: "memory");
        }
    }
    if (stage && t < 32)
        g_s[OFF_HT + (long long)(grp*2+dir)*Bz*Hz + (long long)b*Hz + slice*32 + t] = hlast;
}

// fused: plain norm + 10 weighted norms per (arr, r);  arr = which*2+dir
__global__ void norms_all_kernel(const float* __restrict__ w3, const float* __restrict__ w4){
    int id = blockIdx.x;                 // 4*B*S
    int arr = id / (Bz*Sz), r = id % (Bz*Sz);
    const float* w = (arr & 1) ? w4 : w3;
    __shared__ float red[Lz+1][8];
    int tid = threadIdx.x, wp = tid >> 5, lane = tid & 31;
    float x = g_s[OFF_HS + (long long)arr*BSH + (long long)r*Hz + tid];
    float vv = x*x;
    float s0 = warp_sum(vv);
    if (lane == 0) red[Lz][wp] = s0;
    for (int l = 0; l < Lz; l++){
        float wv = __ldg(&w[l*Hz + tid]);
        float s = warp_sum(wv*wv*vv);
        if (lane == 0) red[l][wp] = s;
    }
    __syncthreads();
    if (tid < Lz){
        float s = 0.f;
        #pragma unroll
        for (int i = 0; i < 8; i++) s += red[tid][i];
        g_s[OFF_NLW + (long long)(arr*Bz*Sz + r)*Lz + tid] = sqrtf(s);
    }
    if (tid == Lz){
        float s = 0.f;
        #pragma unroll
        for (int i = 0; i < 8; i++) s += red[Lz][i];
        g_s[OFF_NRM + (long long)arr*Bz*Sz + r] = sqrtf(s);
    }
}

// cosine attention + fused row max/sum
__global__ void att_kernel(){
    int id = blockIdx.x;                 // 2*B*S
    int dir = id / (Bz*Sz), r = id % (Bz*Sz);
    int b = r / Sz;
    __shared__ float v1s[Hz];
    __shared__ float sbs[8], sbm[8];
    int tid = threadIdx.x, w = tid >> 5, lane = tid & 31;
    v1s[tid] = g_s[OFF_HS + (long long)dir*BSH + (long long)r*Hz + tid];
    __syncthreads();
    const float4* v2 = (const float4*)(g_s + OFF_HS + (long long)(2+dir)*BSH + (long long)(b*Sz + tid)*Hz);
    float acc = 0.f;
    #pragma unroll 8
    for (int h4 = 0; h4 < Hz/4; h4++){
        float4 o = v2[h4];
        acc = fmaf(v1s[4*h4+0], o.x, acc);
        acc = fmaf(v1s[4*h4+1], o.y, acc);
        acc = fmaf(v1s[4*h4+2], o.z, acc);
        acc = fmaf(v1s[4*h4+3], o.w, acc);
    }
    float n1 = g_s[OFF_NRM + (long long)dir*Bz*Sz + r];
    float n2 = g_s[OFF_NRM + (long long)(2+dir)*Bz*Sz + b*Sz + tid];
    float d = n1*n2;
    float a = acc / (d > EPSf ? d : EPSf);
    g_s[OFF_ATT + (long long)dir*BSS + (long long)r*Sz + tid] = a;
    float ssum = warp_sum(a);
    float smax = warp_max(a);
    if (lane == 0){ sbs[w] = ssum; sbm[w] = smax; }
    __syncthreads();
    if (tid == 0){
        float tots = 0.f, totm = -3.4e38f;
        #pragma unroll
        for (int i = 0; i < 8; i++){ tots += sbs[i]; totm = fmaxf(totm, sbm[i]); }
        g_s[OFF_ROWSUM + (long long)dir*Bz*Sz + r] = tots;
        if (dir == 0){
            float* mp = g_s + OFF_MVP + (long long)r*AGGz;
            mp[0] = totm;
            mp[1] = tots / (float)Sz;
        }
    }
}

__global__ void colstats_kernel(){
    int dir = blockIdx.x / Bz, b = blockIdx.x % Bz;   // grid 2*B
    int q = threadIdx.x;
    const float* att = g_s + OFF_ATT + (long long)dir*BSS + (long long)b*Sz*Sz;
    float s = 0.f, m = -3.4e38f;
    for (int p = 0; p < Sz; p++){
        float a = att[(long long)p*Sz + q];
        s += a; m = fmaxf(m, a);
    }
    g_s[OFF_COLSUM + (long long)dir*Bz*Sz + b*Sz + q] = s;
    if (dir == 0){
        float* mh = g_s + OFF_MVH + (long long)(b*Sz + q)*AGGz;
        mh[0] = m;
        mh[1] = s / (float)Sz;
    }
}

// mean_h / max_h per (dir,b,p); tid = h
__global__ void statsrow_kernel(){
    int id = blockIdx.x;                 // 2*B*S
    int dir = id / (Bz*Sz), r = id % (Bz*Sz);
    int b = r / Sz;
    __shared__ float arow[Sz];
    int tid = threadIdx.x;
    arow[tid] = g_s[OFF_ATT + (long long)dir*BSS + (long long)r*Sz + tid];
    __syncthreads();
    const float* vh = g_s + OFF_HS + (long long)(2+dir)*BSH + (long long)b*Sz*Hz;
    float sm = 0.f, mx = -3.4e38f;
    for (int q = 0; q < Sz; q++){
        float pr = arow[q] * vh[(long long)q*Hz + tid];
        sm += pr; mx = fmaxf(mx, pr);
    }
    float rs = g_s[OFF_ROWSUM + (long long)dir*Bz*Sz + r];
    g_s[OFF_STATS + (long long)(0*2+dir)*BSH + (long long)r*Hz + tid] = sm / (rs > EPSf ? rs : EPSf);
    g_s[OFF_STATS + (long long)(1*2+dir)*BSH + (long long)r*Hz + tid] = mx;
}

// mean_p / max_p per (dir,b,q); tid = h
__global__ void statscol_kernel(){
    int id = blockIdx.x;                 // 2*B*S
    int dir = id / (Bz*Sz), r = id % (Bz*Sz);
    int b = r / Sz, q = r % Sz;
    __shared__ float acol[Sz];
    int tid = threadIdx.x;
    acol[tid] = g_s[OFF_ATT + (long long)dir*BSS + (long long)(b*Sz + tid)*Sz + q];
    __syncthreads();
    const float* vp = g_s + OFF_HS + (long long)dir*BSH + (long long)b*Sz*Hz;
    float sm = 0.f, mx = -3.4e38f;
    for (int p = 0; p < Sz; p++){
        float pr = acol[p] * vp[(long long)p*Hz + tid];
        sm += pr; mx = fmaxf(mx, pr);
    }
    float cs = g_s[OFF_COLSUM + (long long)dir*Bz*Sz + r];
    g_s[OFF_STATS + (long long)(2*2+dir)*BSH + (long long)r*Hz + tid] = sm / (cs > EPSf ? cs : EPSf);
    g_s[OFF_STATS + (long long)(3*2+dir)*BSH + (long long)r*Hz + tid] = mx;
}

// pairwise matching, single pass: row-max -> mv_p; spill mm -> scratch for colmax
__global__ void __launch_bounds__(256) pairwise_kernel(const float* __restrict__ w3, const float* __restrict__ w4){
    int id = blockIdx.x;                 // 2*B*S
    int dir = id / (Bz*Sz), r = id % (Bz*Sz);
    int b = r / Sz, s = r % Sz;
    const float* w = dir ? w4 : w3;
    __shared__ float w2s[Lz*Hz];
    __shared__ float vrow[Hz];
    __shared__ float red[Lz][8];
    int tid = threadIdx.x, wp = tid >> 5, lane = tid & 31;
    for (int i = tid; i < Lz*Hz; i += 256){ float x = w[i]; w2s[i] = x*x; }
    vrow[tid] = g_s[OFF_HS + (long long)dir*BSH + (long long)r*Hz + tid];
    __syncthreads();
    const float4* other = (const float4*)(g_s + OFF_HS + (long long)(2+dir)*BSH + (long long)(b*Sz + tid)*Hz);
    float acc[Lz];
    #pragma unroll
    for (int l = 0; l < Lz; l++) acc[l] = 0.f;
    for (int h4 = 0; h4 < Hz/4; h4++){
        float4 o = other[h4];
        float p0 = vrow[4*h4+0]*o.x, p1 = vrow[4*h4+1]*o.y;
        float p2 = vrow[4*h4+2]*o.z, p3 = vrow[4*h4+3]*o.w;
        #pragma unroll
        for (int l = 0; l < Lz; l++){
            acc[l] = fmaf(w2s[l*Hz + 4*h4+0], p0, acc[l]);
            acc[l] = fmaf(w2s[l*Hz + 4*h4+1], p1, acc[l]);
            acc[l] = fmaf(w2s[l*Hz + 4*h4+2], p2, acc[l]);
            acc[l] = fmaf(w2s[l*Hz + 4*h4+3], p3, acc[l]);
        }
    }
    const float* nfix = g_s + OFF_NLW + (long long)((0*2+dir)*Bz*Sz + b*Sz + s)*Lz;
    const float* nstr = g_s + OFF_NLW + (long long)((1*2+dir)*Bz*Sz + b*Sz + tid)*Lz;
    float* mmS = g_s + OFF_MMS + (long long)((dir*Bz + b)*Lz)*Sz*Sz;
    #pragma unroll
    for (int l = 0; l < Lz; l++){
        float d = nfix[l]*nstr[l];
        float v = acc[l] / (d > EPSf ? d : EPSf);
        mmS[(long long)l*Sz*Sz + (long long)s*Sz + tid] = v;   // [l][p][q], coalesced
        float m = warp_max(v);
        if (lane == 0) red[l][wp] = m;
    }
    __syncthreads();
    if (tid < Lz){
        float m = red[tid][0];
        #pragma unroll
        for (int i = 1; i < 8; i++) m = fmaxf(m, red[tid][i]);
        g_s[OFF_MVP + (long long)(b*Sz + s)*AGGz + 2 + dir*10 + tid] = m;
    }
}

// column max of mm over p -> mv_h.  grid 2*B*L, 256 threads (tid = q)
__global__ void colmax_kernel(){
    int id = blockIdx.x;
    int dir = id / (Bz*Lz); int rem = id % (Bz*Lz);
    int b = rem / Lz, l = rem % Lz;
    int q = threadIdx.x;
    const float* mmS = g_s + OFF_MMS + ((long long)((dir*Bz + b)*Lz) + l)*Sz*Sz;
    float m = -3.4e38f;
    for (int p = 0; p < Sz; p++) m = fmaxf(m, mmS[(long long)p*Sz + q]);
    g_s[OFF_MVH + (long long)(b*Sz + q)*AGGz + 2 + dir*10 + l] = m;
}

// attentive / max-attentive mp_match, 8 combos
__global__ void mpmatch_kernel(const float* __restrict__ w5, const float* __restrict__ w6,
                               const float* __restrict__ w7, const float* __restrict__ w8){
    int id = blockIdx.x;                 // 8*B*S
    int k = id / (Bz*Sz), r = id % (Bz*Sz);
    int b = r / Sz, s = r % Sz;
    int dir = k & 1;
    int side = k >> 2;                   // 0: mv_p, 1: mv_h
    int arr  = side ? (2+dir) : dir;
    int kind = side ? ((k & 2) ? 3 : 2) : ((k & 2) ? 1 : 0);
    int wsel = k & 3;
    const float* w = (wsel==0) ? w5 : (wsel==1) ? w6 : (wsel==2) ? w7 : w8;
    __shared__ float rnum[Lz][8], rn1[Lz][8], rn2[Lz][8];
    int tid = threadIdx.x, wp = tid >> 5, lane = tid & 31;
    float a  = g_s[OFF_HS + (long long)arr*BSH + (long long)(b*Sz+s)*Hz + tid];
    float bb = g_s[OFF_STATS + (long long)(kind*2+dir)*BSH + (long long)(b*Sz+s)*Hz + tid];
    float ab = a*bb, aa = a*a, b2 = bb*bb;
    for (int l = 0; l < Lz; l++){
        float wv = __ldg(&w[l*Hz + tid]);
        float w2 = wv*wv;
        float num = warp_sum(w2*ab);
        float n1  = warp_sum(w2*aa);
        float n2  = warp_sum(w2*b2);
        if (lane == 0){ rnum[l][wp] = num; rn1[l][wp] = n1; rn2[l][wp] = n2; }
    }
    __syncthreads();
    if (tid < Lz){
        float N = 0.f, A = 0.f, B2 = 0.f;
        #pragma unroll
        for (int i = 0; i < 8; i++){ N += rnum[tid][i]; A += rn1[tid][i]; B2 += rn2[tid][i]; }
        g_s[(side ? OFF_MVH : OFF_MVP) + (long long)(b*Sz + s)*AGGz + 22 + wsel*10 + tid]
            = N / fmaxf(sqrtf(A)*sqrtf(B2), EPSf);
    }
}

__global__ void means_kernel(const float* __restrict__ left, const float* __restrict__ right){
    int which = blockIdx.x >> 2, b = blockIdx.x & 3;   // grid 8, 320 threads
    int d = threadIdx.x;
    if (d >= Dz) return;
    const float* x = which ? right : left;
    float s = 0.f;
    for (int t = 0; t < Sz; t++) s += x[((long long)b*Sz + t)*Dz + d];
    g_s[OFF_MEANS + (long long)which*Bz*Dz + (long long)b*Dz + d] = s / (float)Sz;
}

__global__ void fc1_kernel(const float* __restrict__ fc1_b){
    int b = blockIdx.x;                  // grid B, 512 threads
    int tid = threadIdx.x;
    __shared__ float feat[FEATN + 6];
    for (int i = tid; i < FEATN; i += 512){
        float v;
        if (i < 1024)       v = g_s[OFF_HT + (long long)(i >> 8)*Bz*Hz + (long long)b*Hz + (i & 255)];
        else if (i < 1026)  v = 0.5f;
        else if (i < 1326)  v = g_s[OFF_MEANS + (long long)b*Dz + (i - 1026)];
        else                v = g_s[OFF_MEANS + (long long)Bz*Dz + (long long)b*Dz + (i - 1326)];
        feat[i] = v;
    }
    __syncthreads();
    float acc = fc1_b[tid];
    for (int k = 0; k < FEATN; k++)
        acc = fmaf(feat[k], g_s[OFF_FC1WT + (long long)k*512 + tid], acc);
    g_s[OFF_FC1O + (long long)b*512 + tid] = tanhf(acc);
}

__global__ void fc2_kernel(const float* __restrict__ W2, const float* __restrict__ b2,
                           float* __restrict__ out){
    int b = blockIdx.x;                  // grid B, 512 threads
    int tid = threadIdx.x;
    __shared__ float y[512];
    y[tid] = g_s[OFF_FC1O + (long long)b*512 + tid];
    __syncthreads();
    if (tid < NCLSz){
        float acc = b2[tid];
        for (int o = 0; o < 512; o++) acc = fmaf(y[o], W2[(long long)tid*512 + o], acc);
        out[b*NCLSz + tid] = acc;
    }
}

extern "C" void kernel_launch(void* const* d_in, const int* in_sizes, int n_in,
                              void* d_out, int out_size){
    const float* left      = (const float*)d_in[0];
    const float* right     = (const float*)d_in[1];
    const float* ctx_Wih_f = (const float*)d_in[2];
    const float* ctx_Whh_f = (const float*)d_in[3];
    const float* ctx_b_f   = (const float*)d_in[4];
    const float* ctx_Wih_b = (const float*)d_in[5];
    const float* ctx_Whh_b = (const float*)d_in[6];
    const float* ctx_b_b   = (const float*)d_in[7];
    const float* agg_Wih_f = (const float*)d_in[8];
    const float* agg_Whh_f = (const float*)d_in[9];
    const float* agg_b_f   = (const float*)d_in[10];
    const float* agg_Wih_b = (const float*)d_in[11];
    const float* agg_Whh_b = (const float*)d_in[12];
    const float* agg_b_b   = (const float*)d_in[13];
    const float* mp_w3     = (const float*)d_in[14];
    const float* mp_w4     = (const float*)d_in[15];
    const float* mp_w5     = (const float*)d_in[16];
    const float* mp_w6     = (const float*)d_in[17];
    const float* mp_w7     = (const float*)d_in[18];
    const float* mp_w8     = (const float*)d_in[19];
    const float* fc1_W     = (const float*)d_in[20];
    const float* fc1_b     = (const float*)d_in[21];
    const float* fc2_W     = (const float*)d_in[22];
    const float* fc2_b     = (const float*)d_in[23];
    float* out = (float*)d_out;

    // weight transposes (Wih + fc1)
    transpose2_kernel<<<dim3(128,1,2),256>>>(ctx_Wih_f, ctx_Wih_b, OFF_WIHT_CF, OFF_WIHT_CB, H4z, Dz);
    transpose2_kernel<<<dim3(64,1,2),256>>>(agg_Wih_f, agg_Wih_b, OFF_WIHT_AF, OFF_WIHT_AB, H4z, AGGz);
    transpose_kernel<<<256,256>>>(fc1_W, OFF_FC1WT, 512, FEATN);

    // ctx pre-activation GEMMs, batched over z (left f/b, right f/b)
    gemm4_kernel<<<dim3(16,16,4),256>>>(left, right, 0, 0,
        OFF_WIHT_CF, (long long)Dz*H4z, ctx_b_f, ctx_b_b,
        OFF_PRE_CTX, Bz*Sz, H4z, Dz);

    lstm3_kernel<<<128,256>>>(0, ctx_Whh_f, ctx_Whh_b);

    norms_all_kernel<<<4*Bz*Sz,256>>>(mp_w3, mp_w4);
    att_kernel<<<2*Bz*Sz,256>>>();
    colstats_kernel<<<2*Bz,256>>>();
    statsrow_kernel<<<2*Bz*Sz,256>>>();
    statscol_kernel<<<2*Bz*Sz,256>>>();
    pairwise_kernel<<<2*Bz*Sz,256>>>(mp_w3, mp_w4);
    colmax_kernel<<<2*Bz*Lz,256>>>();
    mpmatch_kernel<<<8*Bz*Sz,256>>>(mp_w5, mp_w6, mp_w7, mp_w8);
    means_kernel<<<8,320>>>(left, right);

    // agg pre-activation GEMMs, batched over z (mv_p f/b, mv_h f/b)
    gemm4_kernel<<<dim3(16,16,4),256>>>(nullptr, nullptr, OFF_MVP, OFF_MVH,
        OFF_WIHT_AF, (long long)AGGz*H4z, agg_b_f, agg_b_b,
        OFF_PRE_AGG, Bz*Sz, H4z, AGGz);

    lstm3_kernel<<<128,256>>>(1, agg_Whh_f, agg_Whh_b);

    fc1_kernel<<<Bz,512>>>(fc1_b);
    fc2_kernel<<<Bz,512>>>(fc2_W, fc2_b, out);
}